// round 16
// baseline (speedup 1.0000x reference)
#include <cuda_runtime.h>
#include <cstdint>
#include <cstddef>

// ---------------- problem constants ----------------
#define B_     2
#define N_     2048
#define DIMX   256
#define NC     3
#define NH     8
#define DHD    64
#define DI     512      /* NH*DHD */
#define FF     192      /* DHD*NC */
#define MTOT   4096     /* B_*N_ */
#define OALL   1536     /* 3*DI  */
#define BHCNT  16       /* B_*NH */
#define KSPLIT 4
#define KRANGE (N_ / KSPLIT)
#define QT     128      /* q-tile */
#define KT     128      /* key-tile per outer iter */
#define FSLAB  48       /* K f-slab rows */
#define VSLAB  32       /* V kj-slab rows */
#define SCALE_F 0.07216878364870322f   /* (NC*DHD)^-0.5 */
#define QSC    (2.0f * SCALE_F)
#define NEG_BIG (-3.4028235e38f)

typedef unsigned long long u64;

// ---------------- packed f32x2 helpers (sm_103a FFMA2) ----------------
__device__ __forceinline__ u64 pk2(float x) {
    u64 d; unsigned int xi = __float_as_uint(x);
    asm("mov.b64 %0, {%1, %1};" : "=l"(d) : "r"(xi));
    return d;
}
__device__ __forceinline__ void fma2(u64 &d, u64 a, u64 b) {
    asm("fma.rn.f32x2 %0, %1, %2, %0;" : "+l"(d) : "l"(a), "l"(b));
}
__device__ __forceinline__ u64 mul2(u64 a, u64 b) {
    u64 d; asm("mul.rn.f32x2 %0, %1, %2;" : "=l"(d) : "l"(a), "l"(b));
    return d;
}
__device__ __forceinline__ float2 up2(u64 d) {
    unsigned int lo, hi;
    asm("mov.b64 {%0, %1}, %2;" : "=r"(lo), "=r"(hi) : "l"(d));
    return make_float2(__uint_as_float(lo), __uint_as_float(hi));
}

// ---------------- cp.async helpers ----------------
__device__ __forceinline__ void cpa16(void* smem_ptr, const void* gptr) {
    unsigned int s = (unsigned int)__cvta_generic_to_shared(smem_ptr);
    asm volatile("cp.async.cg.shared.global [%0], [%1], 16;" :: "r"(s), "l"(gptr));
}
#define CPA_COMMIT()  asm volatile("cp.async.commit_group;")
#define CPA_WAIT0()   asm volatile("cp.async.wait_group 0;")

// ---------------- scratch ----------------
__device__ float g_xt[NC * DIMX * MTOT];
__device__ float g_wt_all[DIMX * OALL];
__device__ float g_wt_out[DI * DIMX];
__device__ float g_Qt[BHCNT * FF * N_];
__device__ float g_Kt[BHCNT * FF * N_];
__device__ float g_Vn[BHCNT * N_ * FF];
__device__ float g_bias[BHCNT * N_];
__device__ float g_Oct[NC * DI * MTOT];
__device__ float g_pO[KSPLIT * BHCNT * N_ * FF];
__device__ float g_pm[KSPLIT * BHCNT * N_];
__device__ float g_pl[KSPLIT * BHCNT * N_];
__device__ unsigned char g_mask[MTOT];

// ---------------- 0) setup: mask canonicalize + weight transposes ----------------
__global__ void k_setup(const void* __restrict__ mask_raw,
                        const float* __restrict__ wq,
                        const float* __restrict__ wkv,
                        const float* __restrict__ wout) {
    const int idx = blockIdx.x * 256 + threadIdx.x;
    if (idx < MTOT) {
        const uint32_t w0 = *(const uint32_t*)mask_raw;
        const bool bytes_mode = ((w0 & 0xFFFFFF00u) != 0u) && (w0 != 0x3F800000u);
        unsigned char v;
        if (bytes_mode) v = ((const unsigned char*)mask_raw)[idx] != 0;
        else            v = ((const uint32_t*)mask_raw)[idx] != 0u;
        g_mask[idx] = v;
    }
    if (idx < DIMX * OALL) {
        const int i = idx / OALL, o = idx % OALL;
        g_wt_all[idx] = (o < DI) ? wq[(size_t)o * DIMX + i]
                                 : wkv[(size_t)(o - DI) * DIMX + i];
    }
    if (idx < DI * DIMX) {
        const int i = idx / DIMX, o = idx % DIMX;
        g_wt_out[idx] = wout[(size_t)o * DI + i];
    }
}

// ---------------- 1) transpose x ----------------
__global__ void k_transpose_x(const float* __restrict__ x) {
    __shared__ float s[NC][32][33];
    const int i0 = blockIdx.x * 32;
    const int m0 = blockIdx.y * 32;
    const int tx = threadIdx.x, ty = threadIdx.y;
    const int ir = i0 + tx, mr = m0 + ty;
    #pragma unroll
    for (int c = 0; c < NC; c++)
        s[c][ty][tx] = x[(size_t)mr * (DIMX * NC) + ir * NC + c];
    __syncthreads();
    const int iw = i0 + ty, mw = m0 + tx;
    #pragma unroll
    for (int c = 0; c < NC; c++)
        g_xt[(size_t)c * DIMX * MTOT + (size_t)iw * MTOT + mw] = s[c][tx][ty];
}

// ---------------- 3) QKV projection SGEMM (at FFMA2-rt3 roofline) ----------------
#define PKC 16
__global__ void __launch_bounds__(256) k_gemm_proj() {
    __shared__ float As[2][PKC][128];
    __shared__ float Bs[2][PKC][128];
    const int c  = blockIdx.z;
    const int m0 = blockIdx.x * 128;
    const int o0 = blockIdx.y * 128;
    const float* A = g_xt + (size_t)c * DIMX * MTOT;
    const int t = threadIdx.x;
    const int tm2 = (t & 15) * 2;
    const int to8 = (t >> 4) * 8;

    u64 acc[4][8];
    #pragma unroll
    for (int j = 0; j < 4; j++)
        #pragma unroll
        for (int oo = 0; oo < 8; oo++) acc[j][oo] = 0ull;

    const int q1 = t >> 5, x41 = (t & 31) << 2;
    const int q2 = (t + 256) >> 5, x42 = ((t + 256) & 31) << 2;

    {
        cpa16(&As[0][q1][x41], &A[(size_t)q1 * MTOT + m0 + x41]);
        cpa16(&As[0][q2][x42], &A[(size_t)q2 * MTOT + m0 + x42]);
        cpa16(&Bs[0][q1][x41], &g_wt_all[(size_t)q1 * OALL + o0 + x41]);
        cpa16(&Bs[0][q2][x42], &g_wt_all[(size_t)q2 * OALL + o0 + x42]);
        CPA_COMMIT();
    }

    const int NCH = DIMX / PKC;
    for (int ki = 0; ki < NCH; ki++) {
        CPA_WAIT0();
        __syncthreads();
        if (ki + 1 < NCH) {
            const int k0 = (ki + 1) * PKC;
            const int nb = (ki + 1) & 1;
            cpa16(&As[nb][q1][x41], &A[(size_t)(k0 + q1) * MTOT + m0 + x41]);
            cpa16(&As[nb][q2][x42], &A[(size_t)(k0 + q2) * MTOT + m0 + x42]);
            cpa16(&Bs[nb][q1][x41], &g_wt_all[(size_t)(k0 + q1) * OALL + o0 + x41]);
            cpa16(&Bs[nb][q2][x42], &g_wt_all[(size_t)(k0 + q2) * OALL + o0 + x42]);
            CPA_COMMIT();
        }
        const int cb = ki & 1;
        #pragma unroll 4
        for (int kk = 0; kk < PKC; kk++) {
            u64 am[4];
            #pragma unroll
            for (int j = 0; j < 4; j++)
                am[j] = *(const u64*)&As[cb][kk][tm2 + 32 * j];
            #pragma unroll
            for (int oo = 0; oo < 8; oo++) {
                const u64 bd = pk2(Bs[cb][kk][to8 + oo]);
                fma2(acc[0][oo], am[0], bd);
                fma2(acc[1][oo], am[1], bd);
                fma2(acc[2][oo], am[2], bd);
                fma2(acc[3][oo], am[3], bd);
            }
        }
    }

    const int obase = o0 + to8;
    #pragma unroll
    for (int j = 0; j < 4; j++) {
        const int m = m0 + tm2 + 32 * j;
        const int b = m >> 11, n = m & 2047;
        if (o0 < 2 * DI) {
            float* dst0 = (o0 < DI) ? g_Qt : g_Kt;
            #pragma unroll
            for (int oo = 0; oo < 8; oo++) {
                const int o = obase + oo;
                const int r = o & 511;
                const int h = r >> 6, d = r & 63;
                const float2 v = up2(acc[j][oo]);
                *(float2*)&dst0[((size_t)(b * NH + h) * FF + c * DHD + d) * N_ + n] = v;
            }
        } else {
            #pragma unroll
            for (int oo = 0; oo < 8; oo++) {
                const int o = obase + oo;
                const int r = o - 2 * DI;
                const int h = r >> 6, d = r & 63;
                const float2 v = up2(acc[j][oo]);
                g_Vn[((size_t)(b * NH + h) * N_ + n) * FF + c * DHD + d] = v.x;
                g_Vn[((size_t)(b * NH + h) * N_ + n + 1) * FF + c * DHD + d] = v.y;
            }
        }
    }
}

// ---------------- 4) per-key bias: mask ? -ksq*SCALE : -BIG ----------------
__global__ void k_bias() {
    const int bh = blockIdx.y;
    const int n  = blockIdx.x * 256 + threadIdx.x;
    const int b  = bh >> 3;
    const float* kp = g_Kt + (size_t)bh * FF * N_ + n;
    float s = 0.f;
    #pragma unroll 4
    for (int f = 0; f < FF; f++) {
        const float v = kp[(size_t)f * N_];
        s = fmaf(v, v, s);
    }
    g_bias[bh * N_ + n] = g_mask[b * N_ + n] ? -s * SCALE_F : NEG_BIG;
}

// ---------------- 5) attention (at FFMA2-rt3 roofline) ----------------
#define ATHR 512
__global__ void __launch_bounds__(ATHR, 1) k_attn() {
    extern __shared__ float sm[];
    float* sQ    = sm;                       // [192][128]
    float* sKs   = sQ + FF * QT;             // [2][48][128]
    float* sVs   = sKs + 2 * FSLAB * KT;     // [2][32][192]
    float* sP    = sVs + 2 * VSLAB * FF;     // [16][8][64]
    float* sBall = sP + 16 * 8 * 64;         // [512]

    const int bh = blockIdx.y;
    const int q0 = blockIdx.x * QT;
    const int z  = blockIdx.z;
    const int t  = threadIdx.x;
    const int w  = t >> 5, l = t & 31;
    const int qb = w * 8;

    const float* Qg = g_Qt + (size_t)bh * FF * N_;
    const float* Kg = g_Kt + (size_t)bh * FF * N_;
    const float* Vg = g_Vn + (size_t)bh * N_ * FF;
    const float* bg = g_bias + bh * N_;

    const int kbeg = z * KRANGE, kend = kbeg + KRANGE;

    const int kfl[3] = { (t) >> 5, (t + 512) >> 5, (t + 1024) >> 5 };
    const int kx4    = (t & 31) << 2;
    const int vr [3] = { t / 48, (t + 512) / 48, (t + 1024) / 48 };
    const int vf4[3] = { (t % 48) << 2, ((t + 512) % 48) << 2, ((t + 1024) % 48) << 2 };

    #pragma unroll
    for (int j = 0; j < 3; j++)
        cpa16(&sKs[0 * FSLAB * KT + kfl[j] * KT + kx4],
              &Kg[(size_t)kfl[j] * N_ + kbeg + kx4]);
    CPA_COMMIT();

    #pragma unroll
    for (int j = 0; j < 12; j++) {
        const int p = t + j * ATHR;
        const int f = p >> 5, x4 = (p & 31) << 2;
        float4 qv = *(const float4*)&Qg[(size_t)f * N_ + q0 + x4];
        qv.x *= QSC; qv.y *= QSC; qv.z *= QSC; qv.w *= QSC;
        *(float4*)&sQ[f * QT + x4] = qv;
    }
    sBall[t] = bg[kbeg + t];

    float m_r[8], l_r[8];
    u64 op[8][3];
    #pragma unroll
    for (int i = 0; i < 8; i++) {
        m_r[i] = NEG_BIG; l_r[i] = 0.f;
        op[i][0] = 0ull; op[i][1] = 0ull; op[i][2] = 0ull;
    }

    float* pw = sP + w * 512;
    const int half = l >> 4;
    const int col4 = (l & 15) << 2;

    for (int kt = kbeg; kt < kend; kt += KT) {
        u64 sp[4][4];
        #pragma unroll
        for (int rp = 0; rp < 4; rp++)
            #pragma unroll
            for (int cc = 0; cc < 4; cc++) sp[rp][cc] = 0ull;

        for (int s = 0; s < 4; s++) {
            CPA_WAIT0();
            __syncthreads();
            if (s < 3) {
                const int nb = (s + 1) & 1;
                const int fbase = (s + 1) * FSLAB;
                #pragma unroll
                for (int j = 0; j < 3; j++)
                    cpa16(&sKs[nb * FSLAB * KT + kfl[j] * KT + kx4],
                          &Kg[(size_t)(fbase + kfl[j]) * N_ + kt + kx4]);
                CPA_COMMIT();
            } else {
                #pragma unroll
                for (int j = 0; j < 3; j++)
                    cpa16(&sVs[0 * VSLAB * FF + vr[j] * FF + vf4[j]],
                          &Vg[(size_t)(kt + vr[j]) * FF + vf4[j]]);
                CPA_COMMIT();
            }

            const float* Kslab = &sKs[(s & 1) * FSLAB * KT];
            const float* Qf    = &sQ[s * FSLAB * QT];
            #pragma unroll 4
            for (int fl = 0; fl < FSLAB; fl++) {
                const ulonglong2 qA = *(const ulonglong2*)&Qf[fl * QT + qb];
                const ulonglong2 qB = *(const ulonglong2*)&Qf[fl * QT + qb + 4];
                const float4 kv = *(const float4*)&Kslab[fl * KT + 4 * l];
                const u64 k0 = pk2(kv.x), k1 = pk2(kv.y);
                const u64 k2 = pk2(kv.z), k3 = pk2(kv.w);
                fma2(sp[0][0], qA.x, k0); fma2(sp[0][1], qA.x, k1);
                fma2(sp[0][2], qA.x, k2); fma2(sp[0][3], qA.x, k3);
                fma2(sp[1][0], qA.y, k0); fma2(sp[1][1], qA.y, k1);
                fma2(sp[1][2], qA.y, k2); fma2(sp[1][3], qA.y, k3);
                fma2(sp[2][0], qB.x, k0); fma2(sp[2][1], qB.x, k1);
                fma2(sp[2][2], qB.x, k2); fma2(sp[2][3], qB.x, k3);
                fma2(sp[3][0], qB.y, k0); fma2(sp[3][1], qB.y, k1);
                fma2(sp[3][2], qB.y, k2); fma2(sp[3][3], qB.y, k3);
            }
        }

        float s_[8][4];
        #pragma unroll
        for (int rp = 0; rp < 4; rp++)
            #pragma unroll
            for (int cc = 0; cc < 4; cc++) {
                const float2 e = up2(sp[rp][cc]);
                s_[2 * rp][cc]     = e.x;
                s_[2 * rp + 1][cc] = e.y;
            }
        float bbv[4];
        #pragma unroll
        for (int cc = 0; cc < 4; cc++) bbv[cc] = sBall[kt - kbeg + 4 * l + cc];
        #pragma unroll
        for (int i = 0; i < 8; i++)
            #pragma unroll
            for (int cc = 0; cc < 4; cc++)
                s_[i][cc] = s_[i][cc] + bbv[cc];

        float mt[8];
        #pragma unroll
        for (int i = 0; i < 8; i++)
            mt[i] = fmaxf(fmaxf(s_[i][0], s_[i][1]), fmaxf(s_[i][2], s_[i][3]));
        #pragma unroll
        for (int off = 16; off; off >>= 1)
            #pragma unroll
            for (int i = 0; i < 8; i++)
                mt[i] = fmaxf(mt[i], __shfl_xor_sync(0xffffffffu, mt[i], off));

        float rs[8];
        #pragma unroll
        for (int i = 0; i < 8; i++) {
            const float mn = fmaxf(m_r[i], mt[i]);
            const float al = __expf(m_r[i] - mn);
            m_r[i] = mn;
            float acc = 0.f;
            #pragma unroll
            for (int cc = 0; cc < 4; cc++) {
                s_[i][cc] = __expf(s_[i][cc] - mn);
                acc += s_[i][cc];
            }
            rs[i] = acc;
            l_r[i] *= al;
            const u64 ald = pk2(al);
            op[i][0] = mul2(op[i][0], ald);
            op[i][1] = mul2(op[i][1], ald);
            op[i][2] = mul2(op[i][2], ald);
        }
        #pragma unroll
        for (int off = 16; off; off >>= 1)
            #pragma unroll
            for (int i = 0; i < 8; i++)
                rs[i] += __shfl_xor_sync(0xffffffffu, rs[i], off);
        #pragma unroll
        for (int i = 0; i < 8; i++) l_r[i] += rs[i];

        if (half == 0) {
            #pragma unroll
            for (int i = 0; i < 8; i++)
                *(float4*)&pw[i * 64 + col4] =
                    make_float4(s_[i][0], s_[i][1], s_[i][2], s_[i][3]);
        }
        __syncwarp();

        for (int vs = 0; vs < 4; vs++) {
            CPA_WAIT0();
            __syncthreads();
            if (vs < 3) {
                const int nb = (vs + 1) & 1;
                const int kjb = (vs + 1) * VSLAB;
                #pragma unroll
                for (int j = 0; j < 3; j++)
                    cpa16(&sVs[nb * VSLAB * FF + vr[j] * FF + vf4[j]],
                          &Vg[(size_t)(kt + kjb + vr[j]) * FF + vf4[j]]);
                CPA_COMMIT();
            } else if (kt + KT < kend) {
                #pragma unroll
                for (int j = 0; j < 3; j++)
                    cpa16(&sKs[0 * FSLAB * KT + kfl[j] * KT + kx4],
                          &Kg[(size_t)kfl[j] * N_ + (kt + KT) + kx4]);
                CPA_COMMIT();
            }

            const float* V = &sVs[(vs & 1) * VSLAB * FF];
            const int ph = (vs & 1) * 32;
            #pragma unroll 2
            for (int kj = 0; kj < VSLAB; kj += 2) {
                const u64 v00 = *(const u64*)&V[kj * FF + 2 * l];
                const u64 v01 = *(const u64*)&V[kj * FF + 64 + 2 * l];
                const u64 v02 = *(const u64*)&V[kj * FF + 128 + 2 * l];
                const u64 v10 = *(const u64*)&V[(kj + 1) * FF + 2 * l];
                const u64 v11 = *(const u64*)&V[(kj + 1) * FF + 64 + 2 * l];
                const u64 v12 = *(const u64*)&V[(kj + 1) * FF + 128 + 2 * l];
                #pragma unroll
                for (int i = 0; i < 8; i++) {
                    const float2 pp = *(const float2*)&pw[i * 64 + ph + kj];
                    const u64 p0 = pk2(pp.x);
                    const u64 p1 = pk2(pp.y);
                    fma2(op[i][0], p0, v00);
                    fma2(op[i][1], p0, v01);
                    fma2(op[i][2], p0, v02);
                    fma2(op[i][0], p1, v10);
                    fma2(op[i][1], p1, v11);
                    fma2(op[i][2], p1, v12);
                }
            }

            if (vs == 1) {
                if (half == 1) {
                    #pragma unroll
                    for (int i = 0; i < 8; i++)
                        *(float4*)&pw[i * 64 + col4] =
                            make_float4(s_[i][0], s_[i][1], s_[i][2], s_[i][3]);
                }
                __syncwarp();
            }
        }
    }

    float* pO = g_pO + ((size_t)(z * BHCNT + bh) * N_) * FF;
    #pragma unroll
    for (int i = 0; i < 8; i++) {
        const size_t base = (size_t)(q0 + qb + i) * FF;
        *(u64*)&pO[base + 2 * l]       = op[i][0];
        *(u64*)&pO[base + 64 + 2 * l]  = op[i][1];
        *(u64*)&pO[base + 128 + 2 * l] = op[i][2];
    }
    if (l == 0) {
        const size_t rb = (size_t)(z * BHCNT + bh) * N_ + q0 + qb;
        #pragma unroll
        for (int i = 0; i < 8; i++) {
            g_pm[rb + i] = m_r[i];
            g_pl[rb + i] = l_r[i];
        }
    }
}

// ---------------- 5b) split-KV combine (4-way, float4 reads) ----------------
__global__ void __launch_bounds__(256) k_combine() {
    extern __shared__ float smc[];
    float* sO = smc;                        // [192][68]
    __shared__ float wzs[KSPLIT][64];

    const int bh = blockIdx.y;
    const int q0 = blockIdx.x * 64;
    const int b  = bh >> 3;
    const int h  = bh & 7;
    const int t  = threadIdx.x;

    if (t < 64) {
        float mz[KSPLIT], lz[KSPLIT];
        float M = NEG_BIG;
        #pragma unroll
        for (int z = 0; z < KSPLIT; z++) {
            const size_t r = (size_t)(z * BHCNT + bh) * N_ + q0 + t;
            mz[z] = g_pm[r]; lz[z] = g_pl[r];
            M = fmaxf(M, mz[z]);
        }
        float L = 0.f, ez[KSPLIT];
        #pragma unroll
        for (int z = 0; z < KSPLIT; z++) {
            ez[z] = __expf(mz[z] - M);
            L += lz[z] * ez[z];
        }
        const float inv = 1.f / L;
        #pragma unroll
        for (int z = 0; z < KSPLIT; z++) wzs[z][t] = ez[z] * inv;
    }
    __syncthreads();

    #pragma unroll
    for (int j = 0; j < 12; j++) {
        const int u = t + j * 256;
        const int q = u / 48, f4 = (u % 48) << 2;
        float4 a = make_float4(0.f, 0.f, 0.f, 0.f);
        #pragma unroll
        for (int z = 0; z < KSPLIT; z++) {
            const float* pz = g_pO + ((size_t)(z * BHCNT + bh) * N_ + q0) * FF;
            const float4 v = *(const float4*)&pz[(size_t)q * FF + f4];
            const float wz = wzs[z][q];
            a.x = fmaf(wz, v.x, a.x);
            a.y = fmaf(wz, v.y, a.y);
            a.z = fmaf(wz, v.z, a.z);
            a.w = fmaf(wz, v.w, a.w);
        }
        sO[(f4 + 0) * 68 + q] = a.x;
        sO[(f4 + 1) * 68 + q] = a.y;
        sO[(f4 + 2) * 68 + q] = a.z;
        sO[(f4 + 3) * 68 + q] = a.w;
    }
    __syncthreads();

    #pragma unroll
    for (int j = 0; j < 12; j++) {
        const int u = t + j * 256;
        const int f = u >> 4, q4 = (u & 15) << 2;
        const int cc = f >> 6, d = f & 63;
        const float4 v = *(const float4*)&sO[f * 68 + q4];
        *(float4*)&g_Oct[(size_t)cc * DI * MTOT + (size_t)(h * DHD + d) * MTOT
                         + b * N_ + q0 + q4] = v;
    }
}

// ---------------- 6) output projection SGEMM: 128m x 64o tiles ----------------
__global__ void __launch_bounds__(256, 3) k_gemm_out(float* __restrict__ out) {
    __shared__ float As[2][PKC][128];
    __shared__ float Bs[2][PKC][64];
    const int c  = blockIdx.z;
    const int m0 = blockIdx.x * 128;
    const int o0 = blockIdx.y * 64;
    const float* A = g_Oct + (size_t)c * DI * MTOT;
    const int t = threadIdx.x;
    const int tm2 = (t & 15) * 2;
    const int to4 = (t >> 4) * 4;

    u64 acc[4][4];
    #pragma unroll
    for (int j = 0; j < 4; j++)
        #pragma unroll
        for (int oo = 0; oo < 4; oo++) acc[j][oo] = 0ull;

    const int q1 = t >> 5, x41 = (t & 31) << 2;
    const int q2 = (t + 256) >> 5, x42 = ((t + 256) & 31) << 2;
    const int qb_ = t >> 4, xb4 = (t & 15) << 2;

    {
        cpa16(&As[0][q1][x41], &A[(size_t)q1 * MTOT + m0 + x41]);
        cpa16(&As[0][q2][x42], &A[(size_t)q2 * MTOT + m0 + x42]);
        cpa16(&Bs[0][qb_][xb4], &g_wt_out[(size_t)qb_ * DIMX + o0 + xb4]);
        CPA_COMMIT();
    }

    const int NCH = DI / PKC;
    for (int ki = 0; ki < NCH; ki++) {
        CPA_WAIT0();
        __syncthreads();
        if (ki + 1 < NCH) {
            const int k0 = (ki + 1) * PKC;
            const int nb = (ki + 1) & 1;
            cpa16(&As[nb][q1][x41], &A[(size_t)(k0 + q1) * MTOT + m0 + x41]);
            cpa16(&As[nb][q2][x42], &A[(size_t)(k0 + q2) * MTOT + m0 + x42]);
            cpa16(&Bs[nb][qb_][xb4], &g_wt_out[(size_t)(k0 + qb_) * DIMX + o0 + xb4]);
            CPA_COMMIT();
        }
        const int cb = ki & 1;
        #pragma unroll 4
        for (int kk = 0; kk < PKC; kk++) {
            u64 am[4];
            #pragma unroll
            for (int j = 0; j < 4; j++)
                am[j] = *(const u64*)&As[cb][kk][tm2 + 32 * j];
            #pragma unroll
            for (int oo = 0; oo < 4; oo++) {
                const u64 bd = pk2(Bs[cb][kk][to4 + oo]);
                fma2(acc[0][oo], am[0], bd);
                fma2(acc[1][oo], am[1], bd);
                fma2(acc[2][oo], am[2], bd);
                fma2(acc[3][oo], am[3], bd);
            }
        }
    }

    #pragma unroll
    for (int j = 0; j < 4; j++) {
        const int m = m0 + tm2 + 32 * j;
        #pragma unroll
        for (int oo = 0; oo < 4; oo++) {
            const int o = o0 + to4 + oo;
            const float2 v = up2(acc[j][oo]);
            out[(size_t)m * (DIMX * NC) + o * NC + c] = v.x;
            out[(size_t)(m + 1) * (DIMX * NC) + o * NC + c] = v.y;
        }
    }
}

// ---------------- launch ----------------
extern "C" void kernel_launch(void* const* d_in, const int* in_sizes, int n_in,
                              void* d_out, int out_size) {
    (void)in_sizes; (void)n_in; (void)out_size;
    const float* x    = (const float*)d_in[0];
    const void*  mask = d_in[1];
    const float* wq   = (const float*)d_in[2];
    const float* wkv  = (const float*)d_in[3];
    const float* wout = (const float*)d_in[4];
    float* out = (float*)d_out;

    const size_t ATTN_SMEM =
        (size_t)(FF * QT + 2 * FSLAB * KT + 2 * VSLAB * FF + 16 * 8 * 64 + KRANGE)
        * sizeof(float);                                              // 231424 B
    const size_t COMB_SMEM = (size_t)(FF * 68) * sizeof(float);
    cudaFuncSetAttribute(k_attn, cudaFuncAttributeMaxDynamicSharedMemorySize,
                         (int)ATTN_SMEM);
    cudaFuncSetAttribute(k_combine, cudaFuncAttributeMaxDynamicSharedMemorySize,
                         (int)COMB_SMEM);

    k_setup<<<dim3((DIMX * OALL + 255) / 256), 256>>>(mask, wq, wkv, wout);
    k_transpose_x<<<dim3(DIMX / 32, MTOT / 32), dim3(32, 32)>>>(x);
    k_gemm_proj<<<dim3(MTOT / 128, OALL / 128, NC), 256>>>();
    k_bias<<<dim3(N_ / 256, BHCNT), 256>>>();
    k_attn<<<dim3(N_ / QT, BHCNT, KSPLIT), ATHR, ATTN_SMEM>>>();
    k_combine<<<dim3(N_ / 64, BHCNT), 256, COMB_SMEM>>>();
    k_gemm_out<<<dim3(MTOT / 128, DIMX / 64, NC), 256>>>(out);
}

// round 17
// speedup vs baseline: 1.0243x; 1.0243x over previous
#include <cuda_runtime.h>
#include <cstdint>
#include <cstddef>

// ---------------- problem constants ----------------
#define B_     2
#define N_     2048
#define DIMX   256
#define NC     3
#define NH     8
#define DHD    64
#define DI     512      /* NH*DHD */
#define FF     192      /* DHD*NC */
#define MTOT   4096     /* B_*N_ */
#define OALL   1536     /* 3*DI  */
#define BHCNT  16       /* B_*NH */
#define KSPLIT 4
#define KRANGE (N_ / KSPLIT)
#define QT     128      /* q-tile */
#define KT     128      /* key-tile per outer iter */
#define FSLAB  48       /* K f-slab rows */
#define VSLAB  32       /* V kj-slab rows */
#define SCALE_F 0.07216878364870322f   /* (NC*DHD)^-0.5 */
#define QSC    (2.0f * SCALE_F)
#define NEG_BIG (-3.4028235e38f)

typedef unsigned long long u64;

// ---------------- packed f32x2 helpers (sm_103a FFMA2) ----------------
__device__ __forceinline__ u64 pk2(float x) {
    u64 d; unsigned int xi = __float_as_uint(x);
    asm("mov.b64 %0, {%1, %1};" : "=l"(d) : "r"(xi));
    return d;
}
__device__ __forceinline__ void fma2(u64 &d, u64 a, u64 b) {
    asm("fma.rn.f32x2 %0, %1, %2, %0;" : "+l"(d) : "l"(a), "l"(b));
}
__device__ __forceinline__ u64 mul2(u64 a, u64 b) {
    u64 d; asm("mul.rn.f32x2 %0, %1, %2;" : "=l"(d) : "l"(a), "l"(b));
    return d;
}
__device__ __forceinline__ float2 up2(u64 d) {
    unsigned int lo, hi;
    asm("mov.b64 {%0, %1}, %2;" : "=r"(lo), "=r"(hi) : "l"(d));
    return make_float2(__uint_as_float(lo), __uint_as_float(hi));
}

// ---------------- cp.async helpers ----------------
__device__ __forceinline__ void cpa16(void* smem_ptr, const void* gptr) {
    unsigned int s = (unsigned int)__cvta_generic_to_shared(smem_ptr);
    asm volatile("cp.async.cg.shared.global [%0], [%1], 16;" :: "r"(s), "l"(gptr));
}
#define CPA_COMMIT()  asm volatile("cp.async.commit_group;")
#define CPA_WAIT0()   asm volatile("cp.async.wait_group 0;")

// ---------------- scratch ----------------
__device__ float g_xt[NC * DIMX * MTOT];
__device__ float g_wt_all[DIMX * OALL];
__device__ float g_wt_out[DI * DIMX];
__device__ float g_Qt[BHCNT * FF * N_];
__device__ float g_Kt[BHCNT * FF * N_];
__device__ float g_Vn[BHCNT * N_ * FF];
__device__ float g_ksq[BHCNT * N_];
__device__ float g_Oct[NC * DI * MTOT];
__device__ float g_pO[KSPLIT * BHCNT * N_ * FF];
__device__ float g_pm[KSPLIT * BHCNT * N_];
__device__ float g_pl[KSPLIT * BHCNT * N_];
__device__ unsigned char g_mask[MTOT];

// ---------------- 0) mask canonicalize ----------------
__global__ void k_mask_prep(const void* __restrict__ mask_raw) {
    const uint32_t w0 = *(const uint32_t*)mask_raw;
    const bool bytes_mode = ((w0 & 0xFFFFFF00u) != 0u) && (w0 != 0x3F800000u);
    const int n = blockIdx.x * 256 + threadIdx.x;
    if (n >= MTOT) return;
    unsigned char v;
    if (bytes_mode) v = ((const unsigned char*)mask_raw)[n] != 0;
    else            v = ((const uint32_t*)mask_raw)[n] != 0u;
    g_mask[n] = v;
}

// ---------------- 1) transpose x ----------------
__global__ void k_transpose_x(const float* __restrict__ x) {
    __shared__ float s[NC][32][33];
    const int i0 = blockIdx.x * 32;
    const int m0 = blockIdx.y * 32;
    const int tx = threadIdx.x, ty = threadIdx.y;
    const int ir = i0 + tx, mr = m0 + ty;
    #pragma unroll
    for (int c = 0; c < NC; c++)
        s[c][ty][tx] = x[(size_t)mr * (DIMX * NC) + ir * NC + c];
    __syncthreads();
    const int iw = i0 + ty, mw = m0 + tx;
    #pragma unroll
    for (int c = 0; c < NC; c++)
        g_xt[(size_t)c * DIMX * MTOT + (size_t)iw * MTOT + mw] = s[c][tx][ty];
}

// ---------------- 2) transpose weights ----------------
__global__ void k_transpose_w(const float* __restrict__ wq,
                              const float* __restrict__ wkv,
                              const float* __restrict__ wout) {
    const int idx = blockIdx.x * 256 + threadIdx.x;
    if (idx < DIMX * OALL) {
        const int i = idx / OALL, o = idx % OALL;
        g_wt_all[idx] = (o < DI) ? wq[(size_t)o * DIMX + i]
                                 : wkv[(size_t)(o - DI) * DIMX + i];
    }
    if (idx < DI * DIMX) {
        const int i = idx / DIMX, o = idx % DIMX;
        g_wt_out[idx] = wout[(size_t)o * DI + i];
    }
}

// ---------------- 3) QKV projection SGEMM (at FFMA2-rt3 roofline) ----------------
#define PKC 16
__global__ void __launch_bounds__(256) k_gemm_proj() {
    __shared__ float As[2][PKC][128];
    __shared__ float Bs[2][PKC][128];
    const int c  = blockIdx.z;
    const int m0 = blockIdx.x * 128;
    const int o0 = blockIdx.y * 128;
    const float* A = g_xt + (size_t)c * DIMX * MTOT;
    const int t = threadIdx.x;
    const int tm2 = (t & 15) * 2;
    const int to8 = (t >> 4) * 8;

    u64 acc[4][8];
    #pragma unroll
    for (int j = 0; j < 4; j++)
        #pragma unroll
        for (int oo = 0; oo < 8; oo++) acc[j][oo] = 0ull;

    const int q1 = t >> 5, x41 = (t & 31) << 2;
    const int q2 = (t + 256) >> 5, x42 = ((t + 256) & 31) << 2;

    {
        cpa16(&As[0][q1][x41], &A[(size_t)q1 * MTOT + m0 + x41]);
        cpa16(&As[0][q2][x42], &A[(size_t)q2 * MTOT + m0 + x42]);
        cpa16(&Bs[0][q1][x41], &g_wt_all[(size_t)q1 * OALL + o0 + x41]);
        cpa16(&Bs[0][q2][x42], &g_wt_all[(size_t)q2 * OALL + o0 + x42]);
        CPA_COMMIT();
    }

    const int NCH = DIMX / PKC;
    for (int ki = 0; ki < NCH; ki++) {
        CPA_WAIT0();
        __syncthreads();
        if (ki + 1 < NCH) {
            const int k0 = (ki + 1) * PKC;
            const int nb = (ki + 1) & 1;
            cpa16(&As[nb][q1][x41], &A[(size_t)(k0 + q1) * MTOT + m0 + x41]);
            cpa16(&As[nb][q2][x42], &A[(size_t)(k0 + q2) * MTOT + m0 + x42]);
            cpa16(&Bs[nb][q1][x41], &g_wt_all[(size_t)(k0 + q1) * OALL + o0 + x41]);
            cpa16(&Bs[nb][q2][x42], &g_wt_all[(size_t)(k0 + q2) * OALL + o0 + x42]);
            CPA_COMMIT();
        }
        const int cb = ki & 1;
        #pragma unroll 4
        for (int kk = 0; kk < PKC; kk++) {
            u64 am[4];
            #pragma unroll
            for (int j = 0; j < 4; j++)
                am[j] = *(const u64*)&As[cb][kk][tm2 + 32 * j];
            #pragma unroll
            for (int oo = 0; oo < 8; oo++) {
                const u64 bd = pk2(Bs[cb][kk][to8 + oo]);
                fma2(acc[0][oo], am[0], bd);
                fma2(acc[1][oo], am[1], bd);
                fma2(acc[2][oo], am[2], bd);
                fma2(acc[3][oo], am[3], bd);
            }
        }
    }

    const int obase = o0 + to8;
    #pragma unroll
    for (int j = 0; j < 4; j++) {
        const int m = m0 + tm2 + 32 * j;
        const int b = m >> 11, n = m & 2047;
        if (o0 < 2 * DI) {
            float* dst0 = (o0 < DI) ? g_Qt : g_Kt;
            #pragma unroll
            for (int oo = 0; oo < 8; oo++) {
                const int o = obase + oo;
                const int r = o & 511;
                const int h = r >> 6, d = r & 63;
                const float2 v = up2(acc[j][oo]);
                *(float2*)&dst0[((size_t)(b * NH + h) * FF + c * DHD + d) * N_ + n] = v;
            }
        } else {
            #pragma unroll
            for (int oo = 0; oo < 8; oo++) {
                const int o = obase + oo;
                const int r = o - 2 * DI;
                const int h = r >> 6, d = r & 63;
                const float2 v = up2(acc[j][oo]);
                g_Vn[((size_t)(b * NH + h) * N_ + n) * FF + c * DHD + d] = v.x;
                g_Vn[((size_t)(b * NH + h) * N_ + n + 1) * FF + c * DHD + d] = v.y;
            }
        }
    }
}

// ---------------- 4) k_sq: 4 independent accumulators, full unroll (MLP fix) ----------------
__global__ void k_ksq() {
    const int bh = blockIdx.y;
    const int n  = blockIdx.x * 256 + threadIdx.x;
    const float* kp = g_Kt + (size_t)bh * FF * N_ + n;
    float s0 = 0.f, s1 = 0.f, s2 = 0.f, s3 = 0.f;
    #pragma unroll
    for (int f = 0; f < FF; f += 4) {
        const float v0 = kp[(size_t)(f + 0) * N_];
        const float v1 = kp[(size_t)(f + 1) * N_];
        const float v2 = kp[(size_t)(f + 2) * N_];
        const float v3 = kp[(size_t)(f + 3) * N_];
        s0 = fmaf(v0, v0, s0);
        s1 = fmaf(v1, v1, s1);
        s2 = fmaf(v2, v2, s2);
        s3 = fmaf(v3, v3, s3);
    }
    g_ksq[bh * N_ + n] = (s0 + s1) + (s2 + s3);
}

// ---------------- 5) attention (R15 form — at FFMA2-rt3 roofline) ----------------
#define ATHR 512
__global__ void __launch_bounds__(ATHR, 1) k_attn() {
    extern __shared__ float sm[];
    float* sQ    = sm;                       // [192][128]
    float* sKs   = sQ + FF * QT;             // [2][48][128]
    float* sVs   = sKs + 2 * FSLAB * KT;     // [2][32][192]
    float* sP    = sVs + 2 * VSLAB * FF;     // [16][8][64]
    float* sBall = sP + 16 * 8 * 64;         // [512]

    const int bh = blockIdx.y;
    const int q0 = blockIdx.x * QT;
    const int z  = blockIdx.z;
    const int b  = bh >> 3;
    const int t  = threadIdx.x;
    const int w  = t >> 5, l = t & 31;
    const int qb = w * 8;

    const float* Qg  = g_Qt + (size_t)bh * FF * N_;
    const float* Kg  = g_Kt + (size_t)bh * FF * N_;
    const float* Vg  = g_Vn + (size_t)bh * N_ * FF;
    const float* kqg = g_ksq + bh * N_;
    const unsigned char* mg = g_mask + b * N_;

    const int kbeg = z * KRANGE, kend = kbeg + KRANGE;

    const int kfl[3] = { (t) >> 5, (t + 512) >> 5, (t + 1024) >> 5 };
    const int kx4    = (t & 31) << 2;
    const int vr [3] = { t / 48, (t + 512) / 48, (t + 1024) / 48 };
    const int vf4[3] = { (t % 48) << 2, ((t + 512) % 48) << 2, ((t + 1024) % 48) << 2 };

    #pragma unroll
    for (int j = 0; j < 3; j++)
        cpa16(&sKs[0 * FSLAB * KT + kfl[j] * KT + kx4],
              &Kg[(size_t)kfl[j] * N_ + kbeg + kx4]);
    CPA_COMMIT();

    #pragma unroll
    for (int j = 0; j < 12; j++) {
        const int p = t + j * ATHR;
        const int f = p >> 5, x4 = (p & 31) << 2;
        float4 qv = *(const float4*)&Qg[(size_t)f * N_ + q0 + x4];
        qv.x *= QSC; qv.y *= QSC; qv.z *= QSC; qv.w *= QSC;
        *(float4*)&sQ[f * QT + x4] = qv;
    }
    {
        const int jj = kbeg + t;
        sBall[t] = mg[jj] ? -kqg[jj] * SCALE_F : NEG_BIG;
    }

    float m_r[8], l_r[8];
    u64 op[8][3];
    #pragma unroll
    for (int i = 0; i < 8; i++) {
        m_r[i] = NEG_BIG; l_r[i] = 0.f;
        op[i][0] = 0ull; op[i][1] = 0ull; op[i][2] = 0ull;
    }

    float* pw = sP + w * 512;
    const int half = l >> 4;
    const int col4 = (l & 15) << 2;

    for (int kt = kbeg; kt < kend; kt += KT) {
        u64 sp[4][4];
        #pragma unroll
        for (int rp = 0; rp < 4; rp++)
            #pragma unroll
            for (int cc = 0; cc < 4; cc++) sp[rp][cc] = 0ull;

        for (int s = 0; s < 4; s++) {
            CPA_WAIT0();
            __syncthreads();
            if (s < 3) {
                const int nb = (s + 1) & 1;
                const int fbase = (s + 1) * FSLAB;
                #pragma unroll
                for (int j = 0; j < 3; j++)
                    cpa16(&sKs[nb * FSLAB * KT + kfl[j] * KT + kx4],
                          &Kg[(size_t)(fbase + kfl[j]) * N_ + kt + kx4]);
                CPA_COMMIT();
            } else {
                #pragma unroll
                for (int j = 0; j < 3; j++)
                    cpa16(&sVs[0 * VSLAB * FF + vr[j] * FF + vf4[j]],
                          &Vg[(size_t)(kt + vr[j]) * FF + vf4[j]]);
                CPA_COMMIT();
            }

            const float* Kslab = &sKs[(s & 1) * FSLAB * KT];
            const float* Qf    = &sQ[s * FSLAB * QT];
            #pragma unroll 4
            for (int fl = 0; fl < FSLAB; fl++) {
                const ulonglong2 qA = *(const ulonglong2*)&Qf[fl * QT + qb];
                const ulonglong2 qB = *(const ulonglong2*)&Qf[fl * QT + qb + 4];
                const float4 kv = *(const float4*)&Kslab[fl * KT + 4 * l];
                const u64 k0 = pk2(kv.x), k1 = pk2(kv.y);
                const u64 k2 = pk2(kv.z), k3 = pk2(kv.w);
                fma2(sp[0][0], qA.x, k0); fma2(sp[0][1], qA.x, k1);
                fma2(sp[0][2], qA.x, k2); fma2(sp[0][3], qA.x, k3);
                fma2(sp[1][0], qA.y, k0); fma2(sp[1][1], qA.y, k1);
                fma2(sp[1][2], qA.y, k2); fma2(sp[1][3], qA.y, k3);
                fma2(sp[2][0], qB.x, k0); fma2(sp[2][1], qB.x, k1);
                fma2(sp[2][2], qB.x, k2); fma2(sp[2][3], qB.x, k3);
                fma2(sp[3][0], qB.y, k0); fma2(sp[3][1], qB.y, k1);
                fma2(sp[3][2], qB.y, k2); fma2(sp[3][3], qB.y, k3);
            }
        }

        float s_[8][4];
        #pragma unroll
        for (int rp = 0; rp < 4; rp++)
            #pragma unroll
            for (int cc = 0; cc < 4; cc++) {
                const float2 e = up2(sp[rp][cc]);
                s_[2 * rp][cc]     = e.x;
                s_[2 * rp + 1][cc] = e.y;
            }
        float bbv[4];
        #pragma unroll
        for (int cc = 0; cc < 4; cc++) bbv[cc] = sBall[kt - kbeg + 4 * l + cc];
        #pragma unroll
        for (int i = 0; i < 8; i++)
            #pragma unroll
            for (int cc = 0; cc < 4; cc++)
                s_[i][cc] = s_[i][cc] + bbv[cc];

        float mt[8];
        #pragma unroll
        for (int i = 0; i < 8; i++)
            mt[i] = fmaxf(fmaxf(s_[i][0], s_[i][1]), fmaxf(s_[i][2], s_[i][3]));
        #pragma unroll
        for (int off = 16; off; off >>= 1)
            #pragma unroll
            for (int i = 0; i < 8; i++)
                mt[i] = fmaxf(mt[i], __shfl_xor_sync(0xffffffffu, mt[i], off));

        float rs[8];
        #pragma unroll
        for (int i = 0; i < 8; i++) {
            const float mn = fmaxf(m_r[i], mt[i]);
            const float al = __expf(m_r[i] - mn);
            m_r[i] = mn;
            float acc = 0.f;
            #pragma unroll
            for (int cc = 0; cc < 4; cc++) {
                s_[i][cc] = __expf(s_[i][cc] - mn);
                acc += s_[i][cc];
            }
            rs[i] = acc;
            l_r[i] *= al;
            const u64 ald = pk2(al);
            op[i][0] = mul2(op[i][0], ald);
            op[i][1] = mul2(op[i][1], ald);
            op[i][2] = mul2(op[i][2], ald);
        }
        #pragma unroll
        for (int off = 16; off; off >>= 1)
            #pragma unroll
            for (int i = 0; i < 8; i++)
                rs[i] += __shfl_xor_sync(0xffffffffu, rs[i], off);
        #pragma unroll
        for (int i = 0; i < 8; i++) l_r[i] += rs[i];

        if (half == 0) {
            #pragma unroll
            for (int i = 0; i < 8; i++)
                *(float4*)&pw[i * 64 + col4] =
                    make_float4(s_[i][0], s_[i][1], s_[i][2], s_[i][3]);
        }
        __syncwarp();

        for (int vs = 0; vs < 4; vs++) {
            CPA_WAIT0();
            __syncthreads();
            if (vs < 3) {
                const int nb = (vs + 1) & 1;
                const int kjb = (vs + 1) * VSLAB;
                #pragma unroll
                for (int j = 0; j < 3; j++)
                    cpa16(&sVs[nb * VSLAB * FF + vr[j] * FF + vf4[j]],
                          &Vg[(size_t)(kt + kjb + vr[j]) * FF + vf4[j]]);
                CPA_COMMIT();
            } else if (kt + KT < kend) {
                #pragma unroll
                for (int j = 0; j < 3; j++)
                    cpa16(&sKs[0 * FSLAB * KT + kfl[j] * KT + kx4],
                          &Kg[(size_t)kfl[j] * N_ + (kt + KT) + kx4]);
                CPA_COMMIT();
            }

            const float* V = &sVs[(vs & 1) * VSLAB * FF];
            const int ph = (vs & 1) * 32;
            #pragma unroll 2
            for (int kj = 0; kj < VSLAB; kj += 2) {
                const u64 v00 = *(const u64*)&V[kj * FF + 2 * l];
                const u64 v01 = *(const u64*)&V[kj * FF + 64 + 2 * l];
                const u64 v02 = *(const u64*)&V[kj * FF + 128 + 2 * l];
                const u64 v10 = *(const u64*)&V[(kj + 1) * FF + 2 * l];
                const u64 v11 = *(const u64*)&V[(kj + 1) * FF + 64 + 2 * l];
                const u64 v12 = *(const u64*)&V[(kj + 1) * FF + 128 + 2 * l];
                #pragma unroll
                for (int i = 0; i < 8; i++) {
                    const float2 pp = *(const float2*)&pw[i * 64 + ph + kj];
                    const u64 p0 = pk2(pp.x);
                    const u64 p1 = pk2(pp.y);
                    fma2(op[i][0], p0, v00);
                    fma2(op[i][1], p0, v01);
                    fma2(op[i][2], p0, v02);
                    fma2(op[i][0], p1, v10);
                    fma2(op[i][1], p1, v11);
                    fma2(op[i][2], p1, v12);
                }
            }

            if (vs == 1) {
                if (half == 1) {
                    #pragma unroll
                    for (int i = 0; i < 8; i++)
                        *(float4*)&pw[i * 64 + col4] =
                            make_float4(s_[i][0], s_[i][1], s_[i][2], s_[i][3]);
                }
                __syncwarp();
            }
        }
    }

    float* pO = g_pO + ((size_t)(z * BHCNT + bh) * N_) * FF;
    #pragma unroll
    for (int i = 0; i < 8; i++) {
        const size_t base = (size_t)(q0 + qb + i) * FF;
        *(u64*)&pO[base + 2 * l]       = op[i][0];
        *(u64*)&pO[base + 64 + 2 * l]  = op[i][1];
        *(u64*)&pO[base + 128 + 2 * l] = op[i][2];
    }
    if (l == 0) {
        const size_t rb = (size_t)(z * BHCNT + bh) * N_ + q0 + qb;
        #pragma unroll
        for (int i = 0; i < 8; i++) {
            g_pm[rb + i] = m_r[i];
            g_pl[rb + i] = l_r[i];
        }
    }
}

// ---------------- 5b) split-KV combine (4-way, float4 reads) ----------------
__global__ void __launch_bounds__(256) k_combine() {
    extern __shared__ float smc[];
    float* sO = smc;                        // [192][68]
    __shared__ float wzs[KSPLIT][64];

    const int bh = blockIdx.y;
    const int q0 = blockIdx.x * 64;
    const int b  = bh >> 3;
    const int h  = bh & 7;
    const int t  = threadIdx.x;

    if (t < 64) {
        float mz[KSPLIT], lz[KSPLIT];
        float M = NEG_BIG;
        #pragma unroll
        for (int z = 0; z < KSPLIT; z++) {
            const size_t r = (size_t)(z * BHCNT + bh) * N_ + q0 + t;
            mz[z] = g_pm[r]; lz[z] = g_pl[r];
            M = fmaxf(M, mz[z]);
        }
        float L = 0.f, ez[KSPLIT];
        #pragma unroll
        for (int z = 0; z < KSPLIT; z++) {
            ez[z] = __expf(mz[z] - M);
            L += lz[z] * ez[z];
        }
        const float inv = 1.f / L;
        #pragma unroll
        for (int z = 0; z < KSPLIT; z++) wzs[z][t] = ez[z] * inv;
    }
    __syncthreads();

    #pragma unroll
    for (int j = 0; j < 12; j++) {
        const int u = t + j * 256;
        const int q = u / 48, f4 = (u % 48) << 2;
        float4 a = make_float4(0.f, 0.f, 0.f, 0.f);
        #pragma unroll
        for (int z = 0; z < KSPLIT; z++) {
            const float* pz = g_pO + ((size_t)(z * BHCNT + bh) * N_ + q0) * FF;
            const float4 v = *(const float4*)&pz[(size_t)q * FF + f4];
            const float wz = wzs[z][q];
            a.x = fmaf(wz, v.x, a.x);
            a.y = fmaf(wz, v.y, a.y);
            a.z = fmaf(wz, v.z, a.z);
            a.w = fmaf(wz, v.w, a.w);
        }
        sO[(f4 + 0) * 68 + q] = a.x;
        sO[(f4 + 1) * 68 + q] = a.y;
        sO[(f4 + 2) * 68 + q] = a.z;
        sO[(f4 + 3) * 68 + q] = a.w;
    }
    __syncthreads();

    #pragma unroll
    for (int j = 0; j < 12; j++) {
        const int u = t + j * 256;
        const int f = u >> 4, q4 = (u & 15) << 2;
        const int cc = f >> 6, d = f & 63;
        const float4 v = *(const float4*)&sO[f * 68 + q4];
        *(float4*)&g_Oct[(size_t)cc * DI * MTOT + (size_t)(h * DHD + d) * MTOT
                         + b * N_ + q0 + q4] = v;
    }
}

// ---------------- 6) output projection SGEMM: 128m x 64o tiles ----------------
__global__ void __launch_bounds__(256, 3) k_gemm_out(float* __restrict__ out) {
    __shared__ float As[2][PKC][128];
    __shared__ float Bs[2][PKC][64];
    const int c  = blockIdx.z;
    const int m0 = blockIdx.x * 128;
    const int o0 = blockIdx.y * 64;
    const float* A = g_Oct + (size_t)c * DI * MTOT;
    const int t = threadIdx.x;
    const int tm2 = (t & 15) * 2;
    const int to4 = (t >> 4) * 4;

    u64 acc[4][4];
    #pragma unroll
    for (int j = 0; j < 4; j++)
        #pragma unroll
        for (int oo = 0; oo < 4; oo++) acc[j][oo] = 0ull;

    const int q1 = t >> 5, x41 = (t & 31) << 2;
    const int q2 = (t + 256) >> 5, x42 = ((t + 256) & 31) << 2;
    const int qb_ = t >> 4, xb4 = (t & 15) << 2;

    {
        cpa16(&As[0][q1][x41], &A[(size_t)q1 * MTOT + m0 + x41]);
        cpa16(&As[0][q2][x42], &A[(size_t)q2 * MTOT + m0 + x42]);
        cpa16(&Bs[0][qb_][xb4], &g_wt_out[(size_t)qb_ * DIMX + o0 + xb4]);
        CPA_COMMIT();
    }

    const int NCH = DI / PKC;
    for (int ki = 0; ki < NCH; ki++) {
        CPA_WAIT0();
        __syncthreads();
        if (ki + 1 < NCH) {
            const int k0 = (ki + 1) * PKC;
            const int nb = (ki + 1) & 1;
            cpa16(&As[nb][q1][x41], &A[(size_t)(k0 + q1) * MTOT + m0 + x41]);
            cpa16(&As[nb][q2][x42], &A[(size_t)(k0 + q2) * MTOT + m0 + x42]);
            cpa16(&Bs[nb][qb_][xb4], &g_wt_out[(size_t)(k0 + qb_) * DIMX + o0 + xb4]);
            CPA_COMMIT();
        }
        const int cb = ki & 1;
        #pragma unroll 4
        for (int kk = 0; kk < PKC; kk++) {
            u64 am[4];
            #pragma unroll
            for (int j = 0; j < 4; j++)
                am[j] = *(const u64*)&As[cb][kk][tm2 + 32 * j];
            #pragma unroll
            for (int oo = 0; oo < 4; oo++) {
                const u64 bd = pk2(Bs[cb][kk][to4 + oo]);
                fma2(acc[0][oo], am[0], bd);
                fma2(acc[1][oo], am[1], bd);
                fma2(acc[2][oo], am[2], bd);
                fma2(acc[3][oo], am[3], bd);
            }
        }
    }

    #pragma unroll
    for (int j = 0; j < 4; j++) {
        const int m = m0 + tm2 + 32 * j;
        #pragma unroll
        for (int oo = 0; oo < 4; oo++) {
            const int o = o0 + to4 + oo;
            const float2 v = up2(acc[j][oo]);
            out[(size_t)m * (DIMX * NC) + o * NC + c] = v.x;
            out[(size_t)(m + 1) * (DIMX * NC) + o * NC + c] = v.y;
        }
    }
}

// ---------------- launch ----------------
extern "C" void kernel_launch(void* const* d_in, const int* in_sizes, int n_in,
                              void* d_out, int out_size) {
    (void)in_sizes; (void)n_in; (void)out_size;
    const float* x    = (const float*)d_in[0];
    const void*  mask = d_in[1];
    const float* wq   = (const float*)d_in[2];
    const float* wkv  = (const float*)d_in[3];
    const float* wout = (const float*)d_in[4];
    float* out = (float*)d_out;

    const size_t ATTN_SMEM =
        (size_t)(FF * QT + 2 * FSLAB * KT + 2 * VSLAB * FF + 16 * 8 * 64 + KRANGE)
        * sizeof(float);                                              // 231424 B
    const size_t COMB_SMEM = (size_t)(FF * 68) * sizeof(float);
    cudaFuncSetAttribute(k_attn, cudaFuncAttributeMaxDynamicSharedMemorySize,
                         (int)ATTN_SMEM);
    cudaFuncSetAttribute(k_combine, cudaFuncAttributeMaxDynamicSharedMemorySize,
                         (int)COMB_SMEM);

    k_mask_prep<<<dim3((MTOT + 255) / 256), 256>>>(mask);
    k_transpose_x<<<dim3(DIMX / 32, MTOT / 32), dim3(32, 32)>>>(x);
    k_transpose_w<<<dim3((DIMX * OALL + 255) / 256), 256>>>(wq, wkv, wout);
    k_gemm_proj<<<dim3(MTOT / 128, OALL / 128, NC), 256>>>();
    k_ksq<<<dim3(N_ / 256, BHCNT), 256>>>();
    k_attn<<<dim3(N_ / QT, BHCNT, KSPLIT), ATHR, ATTN_SMEM>>>();
    k_combine<<<dim3(N_ / 64, BHCNT), 256, COMB_SMEM>>>();
    k_gemm_out<<<dim3(MTOT / 128, DIMX / 64, NC), 256>>>(out);
}